// round 16
// baseline (speedup 1.0000x reference)
#include <cuda_runtime.h>
#include <cuda_bf16.h>
#include <math.h>

// GCN: N<=100000, E<=1280000, 18 -> 32 -> 64 -> 2, log_softmax.
// Slot-CSR (deg<=64, Poisson(12.8)). 4 kernels + 1 memset.
// QUAD-node layout: quarter-warp (8 lanes) per node, lane = feature QUAD
// (2x f32x2). Gather via ld.global.nc.v2.u64 + packed add.rn.f32x2 (13 inst
// per 16 node-edges, MLP=4). agg2 epilogue: t staged via smem (no shfl),
// W2 pre-interleaved as (W[2fp][c],W[2fp+1][c]) u64 pairs -> one ffma2 = 2
// MACs, one 8KB W2 sweep serves 4 nodes (20 LDS phases/node vs 32).

#define MAXN 100000
#define SLOT_SHIFT 6
#define FULL 0xffffffffu

typedef unsigned long long u64;

__device__ int    g_cursor[MAXN];          // zeroed, becomes degree after scatter
__device__ int    g_csr[MAXN << SLOT_SHIFT];
__device__ float2 g_meta[MAXN];            // (dinv, bitcast deg)
__device__ float  g_p [MAXN * 32];         // dinv[i] * (x @ W1)[i]
__device__ float  g_hs[MAXN * 32];         // dinv[i] * relu(layer1)[i]

// ---------------- packed f32x2 helpers ----------------

__device__ __forceinline__ void ld4(const float* p, u64& a, u64& b) {
    asm("ld.global.nc.v2.u64 {%0,%1}, [%2];" : "=l"(a), "=l"(b) : "l"(p));
}
__device__ __forceinline__ void fadd2(u64& a, u64 x) {
    asm("add.rn.f32x2 %0, %0, %1;" : "+l"(a) : "l"(x));
}
__device__ __forceinline__ void fmul2(u64& a, u64 b) {
    asm("mul.rn.f32x2 %0, %0, %1;" : "+l"(a) : "l"(b));
}
__device__ __forceinline__ void ffma2(u64& d, u64 a, u64 b) {
    asm("fma.rn.f32x2 %0, %1, %2, %0;" : "+l"(d) : "l"(a), "l"(b));
}
__device__ __forceinline__ u64 pack2(float lo, float hi) {
    u64 r; asm("mov.b64 %0, {%1, %2};" : "=l"(r) : "f"(lo), "f"(hi)); return r;
}
__device__ __forceinline__ void unpack2(u64 v, float& lo, float& hi) {
    asm("mov.b64 {%0, %1}, %2;" : "=f"(lo), "=f"(hi) : "l"(v));
}

// quarter-warp gather: node i_me, lane ql covers features 4*ql .. 4*ql+3.
// cmin = min(cnt over the warp's 4 nodes) -> unpredicated common loop;
// per-quarter scalar tail covers the rest. Returns packed pairs (ra, rb).
__device__ __forceinline__ void gather_quarter(const float* __restrict__ feat,
                                               int i_me, int ql, int cnt, int cmin,
                                               u64& ra, u64& rb) {
    const int4* cp4 = (const int4*)(g_csr + (i_me << SLOT_SHIFT));
    u64 a0, b0;
    ld4(feat + i_me * 32 + ql * 4, a0, b0);    // self loop (pre-scaled row)
    u64 a1 = 0, b1 = 0, a2 = 0, b2 = 0, a3 = 0, b3 = 0;
    int full4 = cmin >> 2;
    for (int q = 0; q < full4; q++) {
        int4 j = __ldg(cp4 + q);
        u64 x, y;
        ld4(feat + j.x * 32 + ql * 4, x, y); fadd2(a0, x); fadd2(b0, y);
        ld4(feat + j.y * 32 + ql * 4, x, y); fadd2(a1, x); fadd2(b1, y);
        ld4(feat + j.z * 32 + ql * 4, x, y); fadd2(a2, x); fadd2(b2, y);
        ld4(feat + j.w * 32 + ql * 4, x, y); fadd2(a3, x); fadd2(b3, y);
    }
    const int* cp = (const int*)cp4;
    for (int k = full4 * 4; k < cnt; k++) {
        int j = __ldg(cp + k);
        u64 x, y;
        ld4(feat + j * 32 + ql * 4, x, y); fadd2(a0, x); fadd2(b0, y);
    }
    fadd2(a0, a1); fadd2(a2, a3); fadd2(a0, a2);
    fadd2(b0, b1); fadd2(b2, b3); fadd2(b0, b2);
    ra = a0; rb = b0;
}

// ---------------- scatter edges into slot-CSR ----------------

__global__ void k_scatter(const int* __restrict__ src, const int* __restrict__ dst, int e) {
    int i = blockIdx.x * blockDim.x + threadIdx.x;
    if (i < e) {
        int d = dst[i];
        int p = atomicAdd(&g_cursor[d], 1);
        g_csr[(d << SLOT_SHIFT) + p] = src[i];
    }
}

// ---------- meta (dinv,deg) + xw1 pre-scaled: g_p = dinv * (x @ W1) ----------

__global__ void __launch_bounds__(256) k_meta_xw1(const float* __restrict__ x,
                                                  const float* __restrict__ W1, int n) {
    __shared__ float sW1[18 * 32];
    __shared__ float sdinv[256];
    for (int i = threadIdx.x; i < 18 * 32; i += blockDim.x) sW1[i] = W1[i];

    int t  = threadIdx.x;
    int i0 = blockIdx.x * 256;
    int i  = i0 + t;
    float di = 0.f;
    if (i < n) {
        int d = g_cursor[i];
        di = rsqrtf((float)(d + 1));            // +1 self loop
        g_meta[i] = make_float2(di, __int_as_float(d));
    }
    sdinv[t] = di;
    __syncthreads();

    int lane = t & 31;
    int w    = t >> 5;
    int base = i0 + w * 32;
    #pragma unroll 1
    for (int q = 0; q < 32; q++) {
        int node = base + q;
        if (node >= n) break;
        float xv = (lane < 18) ? __ldg(&x[node * 18 + lane]) : 0.f;
        float acc = 0.f;
        #pragma unroll
        for (int k = 0; k < 18; k++) {
            float xk = __shfl_sync(FULL, xv, k);
            acc = fmaf(xk, sW1[k * 32 + lane], acc);
        }
        g_p[node * 32 + lane] = sdinv[w * 32 + q] * acc;
    }
}

// ---- agg1: quarter-warp per node. g_hs = dinv * relu(di*agg(g_p) + b1) ----

__global__ void __launch_bounds__(256) k_agg1(const float* __restrict__ b1, int n) {
    __shared__ __align__(16) float sb1[32];
    if (threadIdx.x < 32) sb1[threadIdx.x] = b1[threadIdx.x];
    __syncthreads();

    int lane = threadIdx.x & 31;
    int qd   = lane >> 3;
    int ql   = lane & 7;
    int warp = (blockIdx.x * blockDim.x + threadIdx.x) >> 5;
    int nw   = (gridDim.x * blockDim.x) >> 5;
    int nquad = (n + 3) >> 2;

    for (int p = warp; p < nquad; p += nw) {
        int node = 4 * p + qd;
        bool valid = node < n;
        int i_me = valid ? node : (n - 1);
        float2 meta = __ldg(&g_meta[i_me]);
        float di = meta.x;
        int cnt  = __float_as_int(meta.y);
        int m = min(cnt, __shfl_xor_sync(FULL, cnt, 8));
        m = min(m, __shfl_xor_sync(FULL, m, 16));
        u64 A, B;
        gather_quarter(g_p, i_me, ql, cnt, m, A, B);
        float t0, t1, t2, t3;
        unpack2(A, t0, t1);
        unpack2(B, t2, t3);
        float4 bb = *(const float4*)(sb1 + ql * 4);
        float4 h;
        h.x = di * fmaxf(fmaf(di, t0, bb.x), 0.f);
        h.y = di * fmaxf(fmaf(di, t1, bb.y), 0.f);
        h.z = di * fmaxf(fmaf(di, t2, bb.z), 0.f);
        h.w = di * fmaxf(fmaf(di, t3, bb.w), 0.f);
        if (valid) *(float4*)(g_hs + i_me * 32 + ql * 4) = h;
    }
}

// ---- agg2: quad gather + smem-staged W2 epilogue + FC + log_softmax ----

__global__ void __launch_bounds__(256) k_agg2(const float* __restrict__ W2,
                                              const float* __restrict__ b2,
                                              const float* __restrict__ Wfc,
                                              const float* __restrict__ bfc,
                                              float* __restrict__ out, int n) {
    __shared__ __align__(16) u64  sWt[16 * 64];   // (W2[2fp][c], W2[2fp+1][c])
    __shared__ __align__(16) u64  sT[8][64];      // per-warp staged t
    __shared__ float sb2[64];
    __shared__ float sWfc[128];
    __shared__ float sbfc[2];
    for (int idx = threadIdx.x; idx < 16 * 64; idx += 256) {
        int fp = idx >> 6, c = idx & 63;
        sWt[idx] = pack2(W2[(2 * fp) * 64 + c], W2[(2 * fp + 1) * 64 + c]);
    }
    if (threadIdx.x < 128) sWfc[threadIdx.x] = Wfc[threadIdx.x];
    if (threadIdx.x < 64)  sb2[threadIdx.x]  = b2[threadIdx.x];
    if (threadIdx.x < 2)   sbfc[threadIdx.x] = bfc[threadIdx.x];
    __syncthreads();

    int lane = threadIdx.x & 31;
    int w    = threadIdx.x >> 5;      // warp in block
    int qd   = lane >> 3;
    int ql   = lane & 7;
    int warp = (blockIdx.x * blockDim.x + threadIdx.x) >> 5;
    int nw   = (gridDim.x * blockDim.x) >> 5;
    int nquad = (n + 3) >> 2;

    for (int p = warp; p < nquad; p += nw) {
        int node = 4 * p + qd;
        bool valid = node < n;
        int i_me = valid ? node : (n - 1);
        float2 meta = __ldg(&g_meta[i_me]);
        float di = meta.x;
        int cnt  = __float_as_int(meta.y);
        int m = min(cnt, __shfl_xor_sync(FULL, cnt, 8));
        m = min(m, __shfl_xor_sync(FULL, m, 16));
        u64 A, B;
        gather_quarter(g_hs, i_me, ql, cnt, m, A, B);
        u64 di2 = pack2(di, di);
        fmul2(A, di2);
        fmul2(B, di2);

        // stage t for this warp's 4 nodes (16B/lane), quarter-local sharing
        __syncwarp();                               // prior reads done
        {
            ulonglong2 tv; tv.x = A; tv.y = B;
            *((ulonglong2*)(sT[w] + lane * 2)) = tv;
        }
        __syncwarp();

        // W2 sweep: lane owns output cols ql*8 .. ql*8+7 of its node.
        // acc[k] = (even-f partial, odd-f partial) for col ql*8+k.
        u64 acc[8] = {0, 0, 0, 0, 0, 0, 0, 0};
        int tbase = qd * 16;
        #pragma unroll
        for (int fp = 0; fp < 16; fp++) {
            u64 tp = sT[w][tbase + fp];             // (t_{2fp}, t_{2fp+1})
            const ulonglong2* wp = (const ulonglong2*)(sWt + fp * 64 + ql * 8);
            ulonglong2 w01 = wp[0], w23 = wp[1], w45 = wp[2], w67 = wp[3];
            ffma2(acc[0], tp, w01.x); ffma2(acc[1], tp, w01.y);
            ffma2(acc[2], tp, w23.x); ffma2(acc[3], tp, w23.y);
            ffma2(acc[4], tp, w45.x); ffma2(acc[5], tp, w45.y);
            ffma2(acc[6], tp, w67.x); ffma2(acc[7], tp, w67.y);
        }

        // bias + relu + FC partials over this lane's 8 cols
        float p0 = 0.f, p1 = 0.f;
        #pragma unroll
        for (int k = 0; k < 8; k++) {
            int c = ql * 8 + k;
            float lo, hi;
            unpack2(acc[k], lo, hi);
            float h = fmaxf((lo + hi) + sb2[c], 0.f);
            p0 = fmaf(h, sWfc[2 * c],     p0);
            p1 = fmaf(h, sWfc[2 * c + 1], p1);
        }
        // reduce across the 8 lanes of the quarter
        #pragma unroll
        for (int o = 4; o; o >>= 1) {
            p0 += __shfl_xor_sync(FULL, p0, o);
            p1 += __shfl_xor_sync(FULL, p1, o);
        }
        if (ql == 0 && valid) {
            float l0 = p0 + sbfc[0];
            float l1 = p1 + sbfc[1];
            float mx = fmaxf(l0, l1);
            float lse = mx + logf(expf(l0 - mx) + expf(l1 - mx));
            ((float2*)out)[i_me] = make_float2(l0 - lse, l1 - lse);
        }
        __syncwarp();                               // protect sT before next store
    }
}

// ---------------- launch ----------------

extern "C" void kernel_launch(void* const* d_in, const int* in_sizes, int n_in,
                              void* d_out, int out_size) {
    const float* x   = (const float*)d_in[0];
    const int*   ei  = (const int*)d_in[1];
    const float* W1  = (const float*)d_in[2];
    const float* b1  = (const float*)d_in[3];
    const float* W2  = (const float*)d_in[4];
    const float* b2  = (const float*)d_in[5];
    const float* Wfc = (const float*)d_in[6];
    const float* bfc = (const float*)d_in[7];
    float* out = (float*)d_out;

    int n = in_sizes[0] / 18;
    int e = in_sizes[1] / 2;
    const int* src = ei;
    const int* dst = ei + e;

    void* curp = nullptr;
    cudaGetSymbolAddress(&curp, g_cursor);
    cudaMemsetAsync(curp, 0, n * sizeof(int));

    k_scatter<<<(e + 255) / 256, 256>>>(src, dst, e);
    k_meta_xw1<<<(n + 255) / 256, 256>>>(x, W1, n);
    k_agg1<<<1184, 256>>>(b1, n);
    k_agg2<<<1184, 256>>>(W2, b2, Wfc, bfc, out, n);
}

// round 17
// speedup vs baseline: 1.5486x; 1.5486x over previous
#include <cuda_runtime.h>
#include <cuda_bf16.h>
#include <math.h>

// GCN: N<=100000, E<=1280000, 18 -> 32 -> 64 -> 2, log_softmax.
// Slot-CSR (deg<=64, Poisson(12.8)). 4 kernels + 1 memset.
// R12's proven half-warp gather (lane = f32x2 feature pair, LDG.64 => 2 lines
// per warp instruction, MLP=4) kept byte-for-byte. agg2 gathers TWO pairs
// (4 nodes) then runs ONE W2 sweep with interleaved weights
// (W2[2fp][c],W2[2fp+1][c]) u64 pairs: ffma2 = 2 MACs, no pack movs,
// LDS phases/node 32 -> 16.

#define MAXN 100000
#define SLOT_SHIFT 6
#define FULL 0xffffffffu

typedef unsigned long long u64;

__device__ int    g_cursor[MAXN];          // zeroed, becomes degree after scatter
__device__ int    g_csr[MAXN << SLOT_SHIFT];
__device__ float2 g_meta[MAXN];            // (dinv, bitcast deg)
__device__ float  g_p [MAXN * 32];         // dinv[i] * (x @ W1)[i]
__device__ float  g_hs[MAXN * 32];         // dinv[i] * relu(layer1)[i]

// ---------------- packed f32x2 helpers ----------------

__device__ __forceinline__ u64 ld2(const float* p) {
    u64 x; asm("ld.global.nc.b64 %0, [%1];" : "=l"(x) : "l"(p)); return x;
}
__device__ __forceinline__ void fadd2(u64& a, u64 x) {
    asm("add.rn.f32x2 %0, %0, %1;" : "+l"(a) : "l"(x));
}
__device__ __forceinline__ void fmul2(u64& a, u64 b) {
    asm("mul.rn.f32x2 %0, %0, %1;" : "+l"(a) : "l"(b));
}
__device__ __forceinline__ void ffma2(u64& d, u64 a, u64 b) {
    asm("fma.rn.f32x2 %0, %1, %2, %0;" : "+l"(d) : "l"(a), "l"(b));
}
__device__ __forceinline__ u64 pack2(float lo, float hi) {
    u64 r; asm("mov.b64 %0, {%1, %2};" : "=l"(r) : "f"(lo), "f"(hi)); return r;
}
__device__ __forceinline__ void unpack2(u64 v, float& lo, float& hi) {
    asm("mov.b64 {%0, %1}, %2;" : "=f"(lo), "=f"(hi) : "l"(v));
}

// half-warp gather: node i_me, lane covers features 2*hl, 2*hl+1.
// cmin = min(cnt of both nodes in the pair) -> unpredicated common loop;
// per-lane scalar tail covers the rest.  (R12-proven shape: 2 lines/instr.)
__device__ __forceinline__ u64 gather_half(const float* __restrict__ feat,
                                           int i_me, int hl, int cnt, int cmin) {
    const int4* cp4 = (const int4*)(g_csr + (i_me << SLOT_SHIFT));
    u64 a0 = ld2(feat + i_me * 32 + hl * 2);   // self loop (pre-scaled row)
    u64 a1 = 0ull, a2 = 0ull, a3 = 0ull;
    int full4 = cmin >> 2;
    for (int q = 0; q < full4; q++) {
        int4 j = __ldg(cp4 + q);
        fadd2(a0, ld2(feat + j.x * 32 + hl * 2));
        fadd2(a1, ld2(feat + j.y * 32 + hl * 2));
        fadd2(a2, ld2(feat + j.z * 32 + hl * 2));
        fadd2(a3, ld2(feat + j.w * 32 + hl * 2));
    }
    const int* cp = (const int*)cp4;
    for (int k = full4 * 4; k < cnt; k++) {
        int j = __ldg(cp + k);
        fadd2(a0, ld2(feat + j * 32 + hl * 2));
    }
    fadd2(a0, a1); fadd2(a2, a3); fadd2(a0, a2);
    return a0;
}

// ---------------- scatter edges into slot-CSR ----------------

__global__ void k_scatter(const int* __restrict__ src, const int* __restrict__ dst, int e) {
    int i = blockIdx.x * blockDim.x + threadIdx.x;
    if (i < e) {
        int d = dst[i];
        int p = atomicAdd(&g_cursor[d], 1);
        g_csr[(d << SLOT_SHIFT) + p] = src[i];
    }
}

// ---------- meta (dinv,deg) + xw1 pre-scaled: g_p = dinv * (x @ W1) ----------

__global__ void __launch_bounds__(256) k_meta_xw1(const float* __restrict__ x,
                                                  const float* __restrict__ W1, int n) {
    __shared__ float sW1[18 * 32];
    __shared__ float sdinv[256];
    for (int i = threadIdx.x; i < 18 * 32; i += blockDim.x) sW1[i] = W1[i];

    int t  = threadIdx.x;
    int i0 = blockIdx.x * 256;
    int i  = i0 + t;
    float di = 0.f;
    if (i < n) {
        int d = g_cursor[i];
        di = rsqrtf((float)(d + 1));            // +1 self loop
        g_meta[i] = make_float2(di, __int_as_float(d));
    }
    sdinv[t] = di;
    __syncthreads();

    int lane = t & 31;
    int w    = t >> 5;
    int base = i0 + w * 32;
    #pragma unroll 1
    for (int q = 0; q < 32; q++) {
        int node = base + q;
        if (node >= n) break;
        float xv = (lane < 18) ? __ldg(&x[node * 18 + lane]) : 0.f;
        float acc = 0.f;
        #pragma unroll
        for (int k = 0; k < 18; k++) {
            float xk = __shfl_sync(FULL, xv, k);
            acc = fmaf(xk, sW1[k * 32 + lane], acc);
        }
        g_p[node * 32 + lane] = sdinv[w * 32 + q] * acc;
    }
}

// ---- agg1: half-warp per node (R12-identical). ----

__global__ void __launch_bounds__(256) k_agg1(const float* __restrict__ b1, int n) {
    __shared__ __align__(16) float sb1[32];
    if (threadIdx.x < 32) sb1[threadIdx.x] = b1[threadIdx.x];
    __syncthreads();

    int lane = threadIdx.x & 31;
    int hl   = lane & 15;
    bool isB = lane >= 16;
    int warp = (blockIdx.x * blockDim.x + threadIdx.x) >> 5;
    int nw   = (gridDim.x * blockDim.x) >> 5;
    int npair = (n + 1) >> 1;

    for (int p = warp; p < npair; p += nw) {
        int iA  = 2 * p;
        int iBr = 2 * p + 1;
        int i_me = isB ? ((iBr < n) ? iBr : iA) : iA;
        float2 meta = __ldg(&g_meta[i_me]);
        float di = meta.x;
        int cnt  = __float_as_int(meta.y);
        int cntO = __shfl_xor_sync(FULL, cnt, 16);
        u64 s = gather_half(g_p, i_me, hl, cnt, min(cnt, cntO));
        float s_lo, s_hi;
        unpack2(s, s_lo, s_hi);
        float2 bb = *(const float2*)(sb1 + 2 * hl);
        float h_lo = di * fmaxf(fmaf(di, s_lo, bb.x), 0.f);
        float h_hi = di * fmaxf(fmaf(di, s_hi, bb.y), 0.f);
        *(float2*)(g_hs + i_me * 32 + hl * 2) = make_float2(h_lo, h_hi);
    }
}

// ---- agg2: two half-warp gathers (4 nodes) + one interleaved-W2 sweep ----

__global__ void __launch_bounds__(256) k_agg2(const float* __restrict__ W2,
                                              const float* __restrict__ b2,
                                              const float* __restrict__ Wfc,
                                              const float* __restrict__ bfc,
                                              float* __restrict__ out, int n) {
    __shared__ __align__(16) u64 sWt[16 * 64];   // (W2[2fp][c], W2[2fp+1][c])
    __shared__ float sb2[64];
    __shared__ float sWfc[128];
    __shared__ float sbfc[2];
    for (int idx = threadIdx.x; idx < 16 * 64; idx += 256) {
        int fp = idx >> 6, c = idx & 63;
        sWt[idx] = pack2(W2[(2 * fp) * 64 + c], W2[(2 * fp + 1) * 64 + c]);
    }
    if (threadIdx.x < 128) sWfc[threadIdx.x] = Wfc[threadIdx.x];
    if (threadIdx.x < 64)  sb2[threadIdx.x]  = b2[threadIdx.x];
    if (threadIdx.x < 2)   sbfc[threadIdx.x] = bfc[threadIdx.x];
    __syncthreads();

    int lane  = threadIdx.x & 31;
    int hl    = lane & 15;
    int hbase = lane & 16;
    bool isB  = hbase != 0;
    int q4    = hl * 4;                 // lane owns cols q4..q4+3 of its nodes

    int warp = (blockIdx.x * blockDim.x + threadIdx.x) >> 5;
    int nw   = (gridDim.x * blockDim.x) >> 5;
    int nquad = (n + 3) >> 2;

    for (int p = warp; p < nquad; p += nw) {
        int base = 4 * p;
        // pair 1: nodes base, base+1   pair 2: nodes base+2, base+3
        int n1 = base + (isB ? 1 : 0);
        int n2 = base + 2 + (isB ? 1 : 0);
        bool v1 = n1 < n;
        bool v2 = n2 < n;
        int i1 = v1 ? n1 : base;        // base always valid (p < nquad)
        int i2 = v2 ? n2 : base;

        float2 m1 = __ldg(&g_meta[i1]);
        float di1 = m1.x;
        int cnt1  = __float_as_int(m1.y);
        int cmin1 = min(cnt1, __shfl_xor_sync(FULL, cnt1, 16));
        u64 t1 = gather_half(g_hs, i1, hl, cnt1, cmin1);
        fmul2(t1, pack2(di1, di1));

        float2 m2 = __ldg(&g_meta[i2]);
        float di2 = m2.x;
        int cnt2  = __float_as_int(m2.y);
        int cmin2 = min(cnt2, __shfl_xor_sync(FULL, cnt2, 16));
        u64 t2 = gather_half(g_hs, i2, hl, cnt2, cmin2);
        fmul2(t2, pack2(di2, di2));

        // ONE W2 sweep serving all 4 nodes.
        // acc1k accumulates (even-f partial, odd-f partial) of col q4+k, node i1.
        u64 a10 = 0, a11 = 0, a12 = 0, a13 = 0;
        u64 a20 = 0, a21 = 0, a22 = 0, a23 = 0;
        #pragma unroll
        for (int fp = 0; fp < 16; fp++) {
            u64 tb1 = __shfl_sync(FULL, t1, hbase + fp);  // (t_2fp, t_2fp+1) of own half's node
            u64 tb2 = __shfl_sync(FULL, t2, hbase + fp);
            const ulonglong2* wp = (const ulonglong2*)(sWt + fp * 64 + q4);
            ulonglong2 wA = wp[0], wB = wp[1];            // cols q4..q4+3
            ffma2(a10, tb1, wA.x); ffma2(a11, tb1, wA.y);
            ffma2(a12, tb1, wB.x); ffma2(a13, tb1, wB.y);
            ffma2(a20, tb2, wA.x); ffma2(a21, tb2, wA.y);
            ffma2(a22, tb2, wB.x); ffma2(a23, tb2, wB.y);
        }

        // ---- FC + log_softmax, pair 1 ----
        {
            float lo, hi, p0 = 0.f, p1 = 0.f;
            u64 aa[4] = {a10, a11, a12, a13};
            #pragma unroll
            for (int k = 0; k < 4; k++) {
                int c = q4 + k;
                unpack2(aa[k], lo, hi);
                float h = fmaxf((lo + hi) + sb2[c], 0.f);
                p0 = fmaf(h, sWfc[2 * c],     p0);
                p1 = fmaf(h, sWfc[2 * c + 1], p1);
            }
            #pragma unroll
            for (int o = 8; o; o >>= 1) {
                p0 += __shfl_xor_sync(FULL, p0, o);
                p1 += __shfl_xor_sync(FULL, p1, o);
            }
            if (hl == 0 && v1) {
                float l0 = p0 + sbfc[0];
                float l1 = p1 + sbfc[1];
                float mx = fmaxf(l0, l1);
                float lse = mx + logf(expf(l0 - mx) + expf(l1 - mx));
                ((float2*)out)[i1] = make_float2(l0 - lse, l1 - lse);
            }
        }
        // ---- FC + log_softmax, pair 2 ----
        {
            float lo, hi, p0 = 0.f, p1 = 0.f;
            u64 aa[4] = {a20, a21, a22, a23};
            #pragma unroll
            for (int k = 0; k < 4; k++) {
                int c = q4 + k;
                unpack2(aa[k], lo, hi);
                float h = fmaxf((lo + hi) + sb2[c], 0.f);
                p0 = fmaf(h, sWfc[2 * c],     p0);
                p1 = fmaf(h, sWfc[2 * c + 1], p1);
            }
            #pragma unroll
            for (int o = 8; o; o >>= 1) {
                p0 += __shfl_xor_sync(FULL, p0, o);
                p1 += __shfl_xor_sync(FULL, p1, o);
            }
            if (hl == 0 && v2) {
                float l0 = p0 + sbfc[0];
                float l1 = p1 + sbfc[1];
                float mx = fmaxf(l0, l1);
                float lse = mx + logf(expf(l0 - mx) + expf(l1 - mx));
                ((float2*)out)[i2] = make_float2(l0 - lse, l1 - lse);
            }
        }
    }
}

// ---------------- launch ----------------

extern "C" void kernel_launch(void* const* d_in, const int* in_sizes, int n_in,
                              void* d_out, int out_size) {
    const float* x   = (const float*)d_in[0];
    const int*   ei  = (const int*)d_in[1];
    const float* W1  = (const float*)d_in[2];
    const float* b1  = (const float*)d_in[3];
    const float* W2  = (const float*)d_in[4];
    const float* b2  = (const float*)d_in[5];
    const float* Wfc = (const float*)d_in[6];
    const float* bfc = (const float*)d_in[7];
    float* out = (float*)d_out;

    int n = in_sizes[0] / 18;
    int e = in_sizes[1] / 2;
    const int* src = ei;
    const int* dst = ei + e;

    void* curp = nullptr;
    cudaGetSymbolAddress(&curp, g_cursor);
    cudaMemsetAsync(curp, 0, n * sizeof(int));

    k_scatter<<<(e + 255) / 256, 256>>>(src, dst, e);
    k_meta_xw1<<<(n + 255) / 256, 256>>>(x, W1, n);
    k_agg1<<<1184, 256>>>(b1, n);
    k_agg2<<<1184, 256>>>(W2, b2, Wfc, bfc, out, n);
}